// round 1
// baseline (speedup 1.0000x reference)
#include <cuda_runtime.h>
#include <math.h>

#define NBULK        62
#define NSITES       64
#define DDIM         64
#define NBATCH       8192
#define LOGZ_BLOCKS  16
#define PSI_BLOCKS   128
#define TOTAL_BLOCKS (LOGZ_BLOCKS + PSI_BLOCKS)
#define NTHREADS     256

// ---------------- psi-block shared memory layout (float offsets) -------------
#define ENV_STRIDE 68                       // 64 + 4 pad (keeps float4 align, spreads banks)
#define SM_ENV     0                        // 64*68 = 4352 floats
#define SM_A       (64 * ENV_STRIDE)        // 64*128 = 8192 floats (A0|A1 per row)
#define SM_CFG     (SM_A + 64 * 128)        // 4096 bytes = 1024 floats
#define SM_RED     (SM_CFG + 1024)          // 256 floats
#define SM_TOTALF  (SM_RED + 256)           // 13824 floats = 55296 bytes

// ---------------- logz-block shared memory layout ----------------------------
#define LZ_ENV  0                           // 64*65 = 4160 (pad 65 -> conflict-free col reads)
#define LZ_A    4160                        // 8192
#define LZ_TMP  (LZ_A + 8192)               // 64*9 = 576 (pad 9)
#define LZ_RED  (LZ_TMP + 576)              // 256

// ---------------- global scratch (no allocations allowed) --------------------
__device__ float    g_envbuf[2][DDIM * DDIM];
__device__ float    g_maxarr[2][LOGZ_BLOCKS];
__device__ float    g_blocksums[PSI_BLOCKS];
__device__ float    g_logz;
__device__ unsigned g_bar_count;
__device__ volatile unsigned g_bar_gen;

// Software barrier among the LOGZ_BLOCKS cooperating blocks only.
__device__ __forceinline__ void gbar(unsigned target) {
    __syncthreads();
    if (threadIdx.x == 0) {
        __threadfence();
        unsigned t = atomicAdd(&g_bar_count, 1u);
        if (t == LOGZ_BLOCKS - 1) {
            g_bar_count = 0;
            __threadfence();
            g_bar_gen = target;
        } else {
            while (g_bar_gen < target) __nanosleep(64);
        }
    }
    __syncthreads();
    __threadfence();
}

__global__ void init_k() {
    g_bar_count = 0;
    g_bar_gen   = 0;
}

__global__ __launch_bounds__(NTHREADS, 1)
void main_kernel(const int* __restrict__ cfg,
                 const float* __restrict__ left,
                 const float* __restrict__ bulk,
                 const float* __restrict__ right) {
    extern __shared__ float smem[];
    const int tid = threadIdx.x;

    if (blockIdx.x < LOGZ_BLOCKS) {
        // ==================== log-Z path: 16 cooperating blocks ====================
        // env' [i][j] = sum_p sum_{d,e} A_p[d][i] env[d][e] A_p[e][j]
        // block b owns output columns j in [4b, 4b+4)
        unsigned genl = 0;
        const int jb = blockIdx.x << 2;

        if (blockIdx.x == 0) {
            // env0 = left^T @ left  (left is [2][64])
            for (int idx = tid; idx < DDIM * DDIM; idx += NTHREADS) {
                int i = idx >> 6, j = idx & 63;
                g_envbuf[0][idx] = left[i] * left[j] + left[64 + i] * left[64 + j];
            }
        }
        gbar(++genl);

        float inv_scale = 1.0f, log_scale = 0.0f;

        for (int t = 0; t < NBULK; t++) {
            const int cur = t & 1, nxt = cur ^ 1;
            // stage A (both phys slices), coalesced
            const float4* asrc = (const float4*)(bulk + (size_t)t * 8192);
            float4* adst = (float4*)(smem + LZ_A);
#pragma unroll
            for (int i = 0; i < 8; i++) adst[tid + (i << 8)] = asrc[tid + (i << 8)];
            // stage env, applying lazy rescale from previous step
            for (int idx = tid; idx < DDIM * DDIM; idx += NTHREADS) {
                int d = idx >> 6, e = idx & 63;
                smem[LZ_ENV + d * 65 + e] = __ldcg(&g_envbuf[cur][idx]) * inv_scale;
            }
            __syncthreads();

            const int d  = tid & 63;
            const int jj = tid >> 6;
            // phase 1: tmp_p[d][jj] = sum_e env[d][e] * A_p[e][jb+jj]
            float t0 = 0.0f, t1 = 0.0f;
#pragma unroll 8
            for (int e = 0; e < 64; e++) {
                float ev = smem[LZ_ENV + d * 65 + e];
                t0 = fmaf(ev, smem[LZ_A + e * 128 + jb + jj], t0);
                t1 = fmaf(ev, smem[LZ_A + e * 128 + 64 + jb + jj], t1);
            }
            smem[LZ_TMP + d * 9 + jj]     = t0;
            smem[LZ_TMP + d * 9 + 4 + jj] = t1;
            __syncthreads();

            // phase 2: out[i][jb+jj] = sum_p sum_dd A_p[dd][i] * tmp_p[dd][jj]   (i == d)
            float o = 0.0f;
#pragma unroll 8
            for (int dd = 0; dd < 64; dd++) {
                o = fmaf(smem[LZ_A + dd * 128 + d],      smem[LZ_TMP + dd * 9 + jj],     o);
                o = fmaf(smem[LZ_A + dd * 128 + 64 + d], smem[LZ_TMP + dd * 9 + 4 + jj], o);
            }
            g_envbuf[nxt][d * 64 + jb + jj] = o;

            // block max
            smem[LZ_RED + tid] = fabsf(o);
            __syncthreads();
            for (int s = 128; s > 0; s >>= 1) {
                if (tid < s) smem[LZ_RED + tid] = fmaxf(smem[LZ_RED + tid], smem[LZ_RED + tid + s]);
                __syncthreads();
            }
            if (tid == 0) g_maxarr[nxt][blockIdx.x] = smem[LZ_RED];

            gbar(++genl);

            float mx = 0.0f;
#pragma unroll
            for (int b = 0; b < LOGZ_BLOCKS; b++) mx = fmaxf(mx, __ldcg(&g_maxarr[nxt][b]));
            float scale = fmaxf(mx, 1e-30f);
            log_scale += logf(scale);
            inv_scale = 1.0f / scale;
        }

        // final env is in g_envbuf[0] (NBULK even). z = sum(right * (env_scaled @ right))
        if (blockIdx.x == 0) {
            float part = 0.0f;
            if (tid < 128) {
                int k = tid & 63, p = tid >> 6;
                float s = 0.0f;
#pragma unroll 8
                for (int e = 0; e < 64; e++)
                    s = fmaf(__ldcg(&g_envbuf[0][k * 64 + e]), right[e * 2 + p], s);
                part = right[k * 2 + p] * s;
            }
            smem[LZ_RED + tid] = part;
            __syncthreads();
            for (int s = 128; s > 0; s >>= 1) {
                if (tid < s) smem[LZ_RED + tid] += smem[LZ_RED + tid + s];
                __syncthreads();
            }
            if (tid == 0)
                g_logz = logf(fmaxf(smem[LZ_RED] * inv_scale, 1e-30f)) + log_scale;
        }
        return;
    }

    // ==================== psi path: 128 blocks x 64 samples ====================
    const int bi = blockIdx.x - LOGZ_BLOCKS;
    const int m0 = bi * 64;
    unsigned char* cfgS = (unsigned char*)(smem + SM_CFG);

    // stage configurations: cfgS[site][m]
    for (int idx = tid; idx < 64 * 64; idx += NTHREADS) {
        int m = idx >> 6, s = idx & 63;
        cfgS[s * 64 + m] = (unsigned char)cfg[(size_t)(m0 + m) * 64 + s];
    }
    __syncthreads();

    // init env[k][m] = left[cfg0(m)][k]
    for (int idx = tid; idx < 64 * 64; idx += NTHREADS) {
        int k = idx >> 6, m = idx & 63;
        smem[SM_ENV + k * ENV_STRIDE + m] = left[(int)cfgS[m] * 64 + k];
    }

    const int jg = tid & 15;   // 16 groups x 4 outputs j
    const int mg = tid >> 4;   // 16 groups x 4 samples m

    // prefetch A tile for site 0 into registers
    float4 pf[8];
    {
        const float4* src = (const float4*)bulk;
#pragma unroll
        for (int i = 0; i < 8; i++) pf[i] = src[tid + (i << 8)];
    }

    for (int t = 0; t < NBULK; t++) {
        // commit prefetched A tile to SMEM; barrier also publishes env writes of t-1
        float4* adst = (float4*)(smem + SM_A);
#pragma unroll
        for (int i = 0; i < 8; i++) adst[tid + (i << 8)] = pf[i];
        __syncthreads();

        if (t + 1 < NBULK) {
            const float4* src = (const float4*)(bulk + (size_t)(t + 1) * 8192);
#pragma unroll
            for (int i = 0; i < 8; i++) pf[i] = src[tid + (i << 8)];
        }

        const bool s0 = cfgS[(t + 1) * 64 + (mg << 2) + 0] != 0;
        const bool s1 = cfgS[(t + 1) * 64 + (mg << 2) + 1] != 0;
        const bool s2 = cfgS[(t + 1) * 64 + (mg << 2) + 2] != 0;
        const bool s3 = cfgS[(t + 1) * 64 + (mg << 2) + 3] != 0;

        float a00 = 0, a01 = 0, a02 = 0, a03 = 0;
        float a10 = 0, a11 = 0, a12 = 0, a13 = 0;
        float a20 = 0, a21 = 0, a22 = 0, a23 = 0;
        float a30 = 0, a31 = 0, a32 = 0, a33 = 0;

#pragma unroll 4
        for (int k = 0; k < 64; k++) {
            const float4 e  = *(const float4*)&smem[SM_ENV + k * ENV_STRIDE + (mg << 2)];
            const float4 b0 = *(const float4*)&smem[SM_A + k * 128 + (jg << 2)];
            const float4 b1 = *(const float4*)&smem[SM_A + k * 128 + 64 + (jg << 2)];
            {
                float vx = s0 ? b1.x : b0.x, vy = s0 ? b1.y : b0.y,
                      vz = s0 ? b1.z : b0.z, vw = s0 ? b1.w : b0.w;
                a00 = fmaf(e.x, vx, a00); a01 = fmaf(e.x, vy, a01);
                a02 = fmaf(e.x, vz, a02); a03 = fmaf(e.x, vw, a03);
            }
            {
                float vx = s1 ? b1.x : b0.x, vy = s1 ? b1.y : b0.y,
                      vz = s1 ? b1.z : b0.z, vw = s1 ? b1.w : b0.w;
                a10 = fmaf(e.y, vx, a10); a11 = fmaf(e.y, vy, a11);
                a12 = fmaf(e.y, vz, a12); a13 = fmaf(e.y, vw, a13);
            }
            {
                float vx = s2 ? b1.x : b0.x, vy = s2 ? b1.y : b0.y,
                      vz = s2 ? b1.z : b0.z, vw = s2 ? b1.w : b0.w;
                a20 = fmaf(e.z, vx, a20); a21 = fmaf(e.z, vy, a21);
                a22 = fmaf(e.z, vz, a22); a23 = fmaf(e.z, vw, a23);
            }
            {
                float vx = s3 ? b1.x : b0.x, vy = s3 ? b1.y : b0.y,
                      vz = s3 ? b1.z : b0.z, vw = s3 ? b1.w : b0.w;
                a30 = fmaf(e.w, vx, a30); a31 = fmaf(e.w, vy, a31);
                a32 = fmaf(e.w, vz, a32); a33 = fmaf(e.w, vw, a33);
            }
        }
        __syncthreads();   // all k-loop reads done -> safe to overwrite env in place

        // env_new[j][m] = acc ; row j = jg*4+jj , cols m = mg*4..+3
        *(float4*)&smem[SM_ENV + (jg * 4 + 0) * ENV_STRIDE + (mg << 2)] = make_float4(a00, a10, a20, a30);
        *(float4*)&smem[SM_ENV + (jg * 4 + 1) * ENV_STRIDE + (mg << 2)] = make_float4(a01, a11, a21, a31);
        *(float4*)&smem[SM_ENV + (jg * 4 + 2) * ENV_STRIDE + (mg << 2)] = make_float4(a02, a12, a22, a32);
        *(float4*)&smem[SM_ENV + (jg * 4 + 3) * ENV_STRIDE + (mg << 2)] = make_float4(a03, a13, a23, a33);
        // next loop-top __syncthreads publishes these before the next k-loop
    }
    __syncthreads();

    // psi[m] = sum_k env[k][m] * right[k][cfg_last(m)]
    {
        const int m = tid & 63, part = tid >> 6;
        const int sl = cfgS[63 * 64 + m];
        float p = 0.0f;
#pragma unroll
        for (int kk = 0; kk < 16; kk++) {
            int k = part * 16 + kk;
            p = fmaf(smem[SM_ENV + k * ENV_STRIDE + m], right[k * 2 + sl], p);
        }
        smem[SM_RED + tid] = p;
        __syncthreads();
        if (tid < 64) {
            float psi = smem[SM_RED + tid] + smem[SM_RED + 64 + tid] +
                        smem[SM_RED + 128 + tid] + smem[SM_RED + 192 + tid];
            smem[SM_RED + tid] = logf(fmaxf(psi * psi, 1e-12f));
        }
        __syncthreads();
        if (tid == 0) {
            float s = 0.0f;
#pragma unroll 8
            for (int i = 0; i < 64; i++) s += smem[SM_RED + i];
            g_blocksums[bi] = s;
        }
    }
}

__global__ void final_k(float* __restrict__ out) {
    float s = 0.0f;
    for (int i = 0; i < PSI_BLOCKS; i++) s += g_blocksums[i];
    // mean nll = log_z - mean(log |psi|^2)
    out[0] = g_logz - s * (1.0f / (float)NBATCH);
}

extern "C" void kernel_launch(void* const* d_in, const int* in_sizes, int n_in,
                              void* d_out, int out_size) {
    const int*   cfg   = (const int*)d_in[0];
    const float* left  = (const float*)d_in[1];
    const float* bulk  = (const float*)d_in[2];
    const float* right = (const float*)d_in[3];

    cudaFuncSetAttribute(main_kernel, cudaFuncAttributeMaxDynamicSharedMemorySize,
                         SM_TOTALF * 4);

    init_k<<<1, 1>>>();
    main_kernel<<<TOTAL_BLOCKS, NTHREADS, SM_TOTALF * 4>>>(cfg, left, bulk, right);
    final_k<<<1, 1>>>((float*)d_out);
}

// round 2
// speedup vs baseline: 1.0019x; 1.0019x over previous
#include <cuda_runtime.h>
#include <math.h>

#define NBULK        62
#define NSITES       64
#define DDIM         64
#define NBATCH       8192
#define LOGZ_BLOCKS  16
#define PSI_BLOCKS   128
#define TOTAL_BLOCKS (LOGZ_BLOCKS + PSI_BLOCKS)
#define NTHREADS     256

// ---------------- psi-block shared memory layout (float offsets) -------------
#define ENV_STRIDE 68                       // 64 + 4 pad (keeps float4 align, spreads banks)
#define SM_ENV     0                        // 64*68 = 4352 floats
#define SM_A       (64 * ENV_STRIDE)        // 64*128 = 8192 floats (A0|A1 per row)
#define SM_CFG     (SM_A + 64 * 128)        // 4096 bytes = 1024 floats
#define SM_RED     (SM_CFG + 1024)          // 256 floats
#define SM_TOTALF  (SM_RED + 256)           // 13824 floats = 55296 bytes

// ---------------- logz-block shared memory layout ----------------------------
#define LZ_ENV  0                           // 64*65 = 4160 (pad 65 -> conflict-free col reads)
#define LZ_A    4160                        // 8192
#define LZ_TMP  (LZ_A + 8192)               // 64*9 = 576 (pad 9)
#define LZ_RED  (LZ_TMP + 576)              // 256

// ---------------- global scratch (no allocations allowed) --------------------
__device__ float    g_envbuf[2][DDIM * DDIM];
__device__ float    g_maxarr[2][LOGZ_BLOCKS];
__device__ float    g_blocksums[PSI_BLOCKS];
__device__ float    g_logz;
__device__ unsigned g_bar_count;
__device__ volatile unsigned g_bar_gen;

// Software barrier among the LOGZ_BLOCKS cooperating blocks only.
__device__ __forceinline__ void gbar(unsigned target) {
    __syncthreads();
    if (threadIdx.x == 0) {
        __threadfence();
        unsigned t = atomicAdd(&g_bar_count, 1u);
        if (t == LOGZ_BLOCKS - 1) {
            g_bar_count = 0;
            __threadfence();
            g_bar_gen = target;
        } else {
            while (g_bar_gen < target) __nanosleep(64);
        }
    }
    __syncthreads();
    __threadfence();
}

__global__ void init_k() {
    g_bar_count = 0;
    g_bar_gen   = 0;
}

__global__ __launch_bounds__(NTHREADS, 1)
void main_kernel(const int* __restrict__ cfg,
                 const float* __restrict__ left,
                 const float* __restrict__ bulk,
                 const float* __restrict__ right) {
    extern __shared__ float smem[];
    const int tid = threadIdx.x;

    if (blockIdx.x < LOGZ_BLOCKS) {
        // ==================== log-Z path: 16 cooperating blocks ====================
        // env' [i][j] = sum_p sum_{d,e} A_p[d][i] env[d][e] A_p[e][j]
        // block b owns output columns j in [4b, 4b+4)
        unsigned genl = 0;
        const int jb = blockIdx.x << 2;

        if (blockIdx.x == 0) {
            // env0 = left^T @ left  (left is [2][64])
            for (int idx = tid; idx < DDIM * DDIM; idx += NTHREADS) {
                int i = idx >> 6, j = idx & 63;
                g_envbuf[0][idx] = left[i] * left[j] + left[64 + i] * left[64 + j];
            }
        }
        gbar(++genl);

        float inv_scale = 1.0f, log_scale = 0.0f;

        for (int t = 0; t < NBULK; t++) {
            const int cur = t & 1, nxt = cur ^ 1;
            // stage A (both phys slices), coalesced
            const float4* asrc = (const float4*)(bulk + (size_t)t * 8192);
            float4* adst = (float4*)(smem + LZ_A);
#pragma unroll
            for (int i = 0; i < 8; i++) adst[tid + (i << 8)] = asrc[tid + (i << 8)];
            // stage env, applying lazy rescale from previous step
            for (int idx = tid; idx < DDIM * DDIM; idx += NTHREADS) {
                int d = idx >> 6, e = idx & 63;
                smem[LZ_ENV + d * 65 + e] = __ldcg(&g_envbuf[cur][idx]) * inv_scale;
            }
            __syncthreads();

            const int d  = tid & 63;
            const int jj = tid >> 6;
            // phase 1: tmp_p[d][jj] = sum_e env[d][e] * A_p[e][jb+jj]
            float t0 = 0.0f, t1 = 0.0f;
#pragma unroll 8
            for (int e = 0; e < 64; e++) {
                float ev = smem[LZ_ENV + d * 65 + e];
                t0 = fmaf(ev, smem[LZ_A + e * 128 + jb + jj], t0);
                t1 = fmaf(ev, smem[LZ_A + e * 128 + 64 + jb + jj], t1);
            }
            smem[LZ_TMP + d * 9 + jj]     = t0;
            smem[LZ_TMP + d * 9 + 4 + jj] = t1;
            __syncthreads();

            // phase 2: out[i][jb+jj] = sum_p sum_dd A_p[dd][i] * tmp_p[dd][jj]   (i == d)
            float o = 0.0f;
#pragma unroll 8
            for (int dd = 0; dd < 64; dd++) {
                o = fmaf(smem[LZ_A + dd * 128 + d],      smem[LZ_TMP + dd * 9 + jj],     o);
                o = fmaf(smem[LZ_A + dd * 128 + 64 + d], smem[LZ_TMP + dd * 9 + 4 + jj], o);
            }
            g_envbuf[nxt][d * 64 + jb + jj] = o;

            // block max
            smem[LZ_RED + tid] = fabsf(o);
            __syncthreads();
            for (int s = 128; s > 0; s >>= 1) {
                if (tid < s) smem[LZ_RED + tid] = fmaxf(smem[LZ_RED + tid], smem[LZ_RED + tid + s]);
                __syncthreads();
            }
            if (tid == 0) g_maxarr[nxt][blockIdx.x] = smem[LZ_RED];

            gbar(++genl);

            float mx = 0.0f;
#pragma unroll
            for (int b = 0; b < LOGZ_BLOCKS; b++) mx = fmaxf(mx, __ldcg(&g_maxarr[nxt][b]));
            float scale = fmaxf(mx, 1e-30f);
            log_scale += logf(scale);
            inv_scale = 1.0f / scale;
        }

        // final env is in g_envbuf[0] (NBULK even). z = sum(right * (env_scaled @ right))
        if (blockIdx.x == 0) {
            float part = 0.0f;
            if (tid < 128) {
                int k = tid & 63, p = tid >> 6;
                float s = 0.0f;
#pragma unroll 8
                for (int e = 0; e < 64; e++)
                    s = fmaf(__ldcg(&g_envbuf[0][k * 64 + e]), right[e * 2 + p], s);
                part = right[k * 2 + p] * s;
            }
            smem[LZ_RED + tid] = part;
            __syncthreads();
            for (int s = 128; s > 0; s >>= 1) {
                if (tid < s) smem[LZ_RED + tid] += smem[LZ_RED + tid + s];
                __syncthreads();
            }
            if (tid == 0)
                g_logz = logf(fmaxf(smem[LZ_RED] * inv_scale, 1e-30f)) + log_scale;
        }
        return;
    }

    // ==================== psi path: 128 blocks x 64 samples ====================
    const int bi = blockIdx.x - LOGZ_BLOCKS;
    const int m0 = bi * 64;
    unsigned char* cfgS = (unsigned char*)(smem + SM_CFG);

    // stage configurations: cfgS[site][m]
    for (int idx = tid; idx < 64 * 64; idx += NTHREADS) {
        int m = idx >> 6, s = idx & 63;
        cfgS[s * 64 + m] = (unsigned char)cfg[(size_t)(m0 + m) * 64 + s];
    }
    __syncthreads();

    // init env[k][m] = left[cfg0(m)][k]
    for (int idx = tid; idx < 64 * 64; idx += NTHREADS) {
        int k = idx >> 6, m = idx & 63;
        smem[SM_ENV + k * ENV_STRIDE + m] = left[(int)cfgS[m] * 64 + k];
    }

    const int jg = tid & 15;   // 16 groups x 4 outputs j
    const int mg = tid >> 4;   // 16 groups x 4 samples m

    // prefetch A tile for site 0 into registers
    float4 pf[8];
    {
        const float4* src = (const float4*)bulk;
#pragma unroll
        for (int i = 0; i < 8; i++) pf[i] = src[tid + (i << 8)];
    }

    for (int t = 0; t < NBULK; t++) {
        // commit prefetched A tile to SMEM; barrier also publishes env writes of t-1
        float4* adst = (float4*)(smem + SM_A);
#pragma unroll
        for (int i = 0; i < 8; i++) adst[tid + (i << 8)] = pf[i];
        __syncthreads();

        if (t + 1 < NBULK) {
            const float4* src = (const float4*)(bulk + (size_t)(t + 1) * 8192);
#pragma unroll
            for (int i = 0; i < 8; i++) pf[i] = src[tid + (i << 8)];
        }

        const bool s0 = cfgS[(t + 1) * 64 + (mg << 2) + 0] != 0;
        const bool s1 = cfgS[(t + 1) * 64 + (mg << 2) + 1] != 0;
        const bool s2 = cfgS[(t + 1) * 64 + (mg << 2) + 2] != 0;
        const bool s3 = cfgS[(t + 1) * 64 + (mg << 2) + 3] != 0;

        float a00 = 0, a01 = 0, a02 = 0, a03 = 0;
        float a10 = 0, a11 = 0, a12 = 0, a13 = 0;
        float a20 = 0, a21 = 0, a22 = 0, a23 = 0;
        float a30 = 0, a31 = 0, a32 = 0, a33 = 0;

#pragma unroll 4
        for (int k = 0; k < 64; k++) {
            const float4 e  = *(const float4*)&smem[SM_ENV + k * ENV_STRIDE + (mg << 2)];
            const float4 b0 = *(const float4*)&smem[SM_A + k * 128 + (jg << 2)];
            const float4 b1 = *(const float4*)&smem[SM_A + k * 128 + 64 + (jg << 2)];
            {
                float vx = s0 ? b1.x : b0.x, vy = s0 ? b1.y : b0.y,
                      vz = s0 ? b1.z : b0.z, vw = s0 ? b1.w : b0.w;
                a00 = fmaf(e.x, vx, a00); a01 = fmaf(e.x, vy, a01);
                a02 = fmaf(e.x, vz, a02); a03 = fmaf(e.x, vw, a03);
            }
            {
                float vx = s1 ? b1.x : b0.x, vy = s1 ? b1.y : b0.y,
                      vz = s1 ? b1.z : b0.z, vw = s1 ? b1.w : b0.w;
                a10 = fmaf(e.y, vx, a10); a11 = fmaf(e.y, vy, a11);
                a12 = fmaf(e.y, vz, a12); a13 = fmaf(e.y, vw, a13);
            }
            {
                float vx = s2 ? b1.x : b0.x, vy = s2 ? b1.y : b0.y,
                      vz = s2 ? b1.z : b0.z, vw = s2 ? b1.w : b0.w;
                a20 = fmaf(e.z, vx, a20); a21 = fmaf(e.z, vy, a21);
                a22 = fmaf(e.z, vz, a22); a23 = fmaf(e.z, vw, a23);
            }
            {
                float vx = s3 ? b1.x : b0.x, vy = s3 ? b1.y : b0.y,
                      vz = s3 ? b1.z : b0.z, vw = s3 ? b1.w : b0.w;
                a30 = fmaf(e.w, vx, a30); a31 = fmaf(e.w, vy, a31);
                a32 = fmaf(e.w, vz, a32); a33 = fmaf(e.w, vw, a33);
            }
        }
        __syncthreads();   // all k-loop reads done -> safe to overwrite env in place

        // env_new[j][m] = acc ; row j = jg*4+jj , cols m = mg*4..+3
        *(float4*)&smem[SM_ENV + (jg * 4 + 0) * ENV_STRIDE + (mg << 2)] = make_float4(a00, a10, a20, a30);
        *(float4*)&smem[SM_ENV + (jg * 4 + 1) * ENV_STRIDE + (mg << 2)] = make_float4(a01, a11, a21, a31);
        *(float4*)&smem[SM_ENV + (jg * 4 + 2) * ENV_STRIDE + (mg << 2)] = make_float4(a02, a12, a22, a32);
        *(float4*)&smem[SM_ENV + (jg * 4 + 3) * ENV_STRIDE + (mg << 2)] = make_float4(a03, a13, a23, a33);
        // next loop-top __syncthreads publishes these before the next k-loop
    }
    __syncthreads();

    // psi[m] = sum_k env[k][m] * right[k][cfg_last(m)]
    {
        const int m = tid & 63, part = tid >> 6;
        const int sl = cfgS[63 * 64 + m];
        float p = 0.0f;
#pragma unroll
        for (int kk = 0; kk < 16; kk++) {
            int k = part * 16 + kk;
            p = fmaf(smem[SM_ENV + k * ENV_STRIDE + m], right[k * 2 + sl], p);
        }
        smem[SM_RED + tid] = p;
        __syncthreads();
        if (tid < 64) {
            float psi = smem[SM_RED + tid] + smem[SM_RED + 64 + tid] +
                        smem[SM_RED + 128 + tid] + smem[SM_RED + 192 + tid];
            smem[SM_RED + tid] = logf(fmaxf(psi * psi, 1e-12f));
        }
        __syncthreads();
        if (tid == 0) {
            float s = 0.0f;
#pragma unroll 8
            for (int i = 0; i < 64; i++) s += smem[SM_RED + i];
            g_blocksums[bi] = s;
        }
    }
}

__global__ void final_k(float* __restrict__ out) {
    float s = 0.0f;
    for (int i = 0; i < PSI_BLOCKS; i++) s += g_blocksums[i];
    // mean nll = log_z - mean(log |psi|^2)
    out[0] = g_logz - s * (1.0f / (float)NBATCH);
}

extern "C" void kernel_launch(void* const* d_in, const int* in_sizes, int n_in,
                              void* d_out, int out_size) {
    const int*   cfg   = (const int*)d_in[0];
    const float* left  = (const float*)d_in[1];
    const float* bulk  = (const float*)d_in[2];
    const float* right = (const float*)d_in[3];

    cudaFuncSetAttribute(main_kernel, cudaFuncAttributeMaxDynamicSharedMemorySize,
                         SM_TOTALF * 4);

    init_k<<<1, 1>>>();
    main_kernel<<<TOTAL_BLOCKS, NTHREADS, SM_TOTALF * 4>>>(cfg, left, bulk, right);
    final_k<<<1, 1>>>((float*)d_out);
}